// round 5
// baseline (speedup 1.0000x reference)
#include <cuda_runtime.h>
#include <math.h>

#define Tt   512
#define Bb   64
#define INN  128
#define Hh   512
#define Ll   3
#define OUTN 128

// ---------------- scratch (device globals: no runtime allocation) ----------
__device__ float g_bufA[Tt * Bb * Hh];   // 64 MB activation ping
__device__ float g_bufB[Tt * Bb * Hh];   // 64 MB activation pong

// ---------------- packed fp32x2 helpers (B300 FFMA2 path) ------------------
typedef unsigned long long ull;
#define FMA2(d, a, b) asm("fma.rn.f32x2 %0, %1, %2, %0;" : "+l"(d) : "l"(a), "l"(b))
#define UNPK(lo, hi, p) asm("mov.b64 {%0, %1}, %2;" : "=f"(lo), "=f"(hi) : "l"(p))
#define PACK2(p, lo, hi) asm("mov.b64 %0, {%1, %2};" : "=l"(p) : "f"(lo), "f"(hi))

__device__ __forceinline__ unsigned cvta_smem(const void* p) {
    unsigned a;
    asm("{ .reg .u64 t; cvta.to.shared.u64 t, %1; cvt.u32.u64 %0, t; }"
        : "=r"(a) : "l"(p));
    return a;
}
__device__ __forceinline__ unsigned mapa_u32(unsigned addr, unsigned rank) {
    unsigned r;
    asm("mapa.shared::cluster.u32 %0, %1, %2;" : "=r"(r) : "r"(addr), "r"(rank));
    return r;
}
__device__ __forceinline__ void st_async_b64(unsigned raddr, ull v, unsigned rbar) {
    asm volatile(
        "st.async.shared::cluster.mbarrier::complete_tx::bytes.b64 [%0], %1, [%2];"
        :: "r"(raddr), "l"(v), "r"(rbar) : "memory");
}
#define MBAR_INIT(a, n) \
    asm volatile("mbarrier.init.shared.b64 [%0], %1;" :: "r"(a), "r"(n) : "memory")
#define MBAR_EXPECT_TX(a, tx) \
    asm volatile("mbarrier.arrive.expect_tx.shared.b64 _, [%0], %1;" \
                 :: "r"(a), "r"(tx) : "memory")
#define MBAR_WAIT_CLUSTER(a, ph) do {                                          \
    unsigned _dn;                                                              \
    asm volatile("{\n\t.reg .pred p;\n\t"                                      \
        "mbarrier.try_wait.parity.acquire.cluster.shared::cta.b64 p, [%1], %2;\n\t" \
        "selp.b32 %0, 1, 0, p;\n\t}"                                           \
        : "=r"(_dn) : "r"(a), "r"(ph) : "memory");                             \
    while (!_dn) {                                                             \
        asm volatile("{\n\t.reg .pred p;\n\t"                                  \
            "mbarrier.try_wait.parity.acquire.cluster.shared::cta.b64 p, [%1], %2, 0x989680;\n\t" \
            "selp.b32 %0, 1, 0, p;\n\t}"                                       \
            : "=r"(_dn) : "r"(a), "r"(ph) : "memory");                         \
    }                                                                          \
} while (0)

// ---------------- SGEMM: Y[M,N] = X[M,K] @ W[N,K]^T + b1(+b2) --------------
template <int K>
__global__ __launch_bounds__(256) void sgemm_bias(
    const float* __restrict__ X, const float* __restrict__ W,
    const float* __restrict__ b1, const float* __restrict__ b2,
    float* __restrict__ Y, int N)
{
    constexpr int BM = 128, BN = 64, BK = 32, SA = BK + 2;
    __shared__ float Asm[BM * SA];
    __shared__ float Wsm[BN * SA];

    const int tid = threadIdx.x;
    const int r = tid >> 4;
    const int c = tid & 15;
    const int m0 = blockIdx.y * BM;
    const int n0 = blockIdx.x * BN;

    ull acc[8][4];
#pragma unroll
    for (int i = 0; i < 8; i++)
#pragma unroll
        for (int j = 0; j < 4; j++) acc[i][j] = 0ull;

    for (int k0 = 0; k0 < K; k0 += BK) {
#pragma unroll
        for (int i = 0; i < 4; i++) {
            int f = tid + i * 256;
            int m = f >> 3, kq = f & 7;
            float4 v = *(const float4*)&X[(size_t)(m0 + m) * K + k0 + kq * 4];
            float* d = &Asm[m * SA + kq * 4];
            *(float2*)&d[0] = make_float2(v.x, v.y);
            *(float2*)&d[2] = make_float2(v.z, v.w);
        }
#pragma unroll
        for (int i = 0; i < 2; i++) {
            int f = tid + i * 256;
            int n = f >> 3, kq = f & 7;
            float4 v = *(const float4*)&W[(size_t)(n0 + n) * K + k0 + kq * 4];
            float* d = &Wsm[n * SA + kq * 4];
            *(float2*)&d[0] = make_float2(v.x, v.y);
            *(float2*)&d[2] = make_float2(v.z, v.w);
        }
        __syncthreads();

#pragma unroll
        for (int kp = 0; kp < BK / 2; kp++) {
            ull a[8], b[4];
#pragma unroll
            for (int i = 0; i < 8; i++)
                a[i] = *(const ull*)&Asm[(r * 8 + i) * SA + 2 * kp];
#pragma unroll
            for (int j = 0; j < 4; j++)
                b[j] = *(const ull*)&Wsm[(j * 16 + c) * SA + 2 * kp];
#pragma unroll
            for (int i = 0; i < 8; i++)
#pragma unroll
                for (int j = 0; j < 4; j++) FMA2(acc[i][j], a[i], b[j]);
        }
        __syncthreads();
    }

#pragma unroll
    for (int i = 0; i < 8; i++) {
        int m = m0 + r * 8 + i;
#pragma unroll
        for (int j = 0; j < 4; j++) {
            int n = n0 + j * 16 + c;
            float lo, hi;
            UNPK(lo, hi, acc[i][j]);
            float bias = b1[n];
            if (b2) bias += b2[n];
            Y[(size_t)m * N + n] = lo + hi + bias;
        }
    }
}

// ---------------- recurrent scan (8-CTA DSMEM cluster per batch group) -----
// 128 CTAs = 16 clusters (batch groups, 4 b each) x 8 ranks (j-groups, 64 j).
// h exchanged via st.async into every peer's smem double buffer; step start
// is a single local mbarrier parity wait (tx = 8192 bytes = full 4x512 tile).
// W_hh slice in registers (2 j x 64 k per thread, packed f32x2).
__global__ __launch_bounds__(256) __cluster_dims__(8, 1, 1)
void rnn_scan(
    float* __restrict__ act,         // [T,B,H] pre -> overwritten with ys
    const float* __restrict__ Whh,   // [H,H] row-major (j,k)
    const float* __restrict__ h0l,   // [B,H]
    float* __restrict__ hout)        // [B,H] final hidden
{
    __shared__ __align__(16) float hsm[2][4 * Hh];   // 16 KB recv double buffer
    __shared__ __align__(16) float red[8 * 256];     // k-split reduction
    __shared__ __align__(8)  ull  mbarr[2];

    const int tid = threadIdx.x;
    const int jq  = tid & 31;        // 0..31 -> 2 j each
    const int ks  = tid >> 5;        // 0..7  -> 64 k each
    const int jg  = blockIdx.x & 7;  // == cluster rank
    const int bg  = blockIdx.x >> 3;
    const int j0  = jg * 64;
    const int b0  = bg * 4;
    const int kbase = ks * 64;

    // ---- persistent W slice in registers ----
    ull w0[32], w1[32];
    {
        const float* r0 = &Whh[(size_t)(j0 + 2 * jq + 0) * Hh + kbase];
        const float* r1 = &Whh[(size_t)(j0 + 2 * jq + 1) * Hh + kbase];
#pragma unroll
        for (int kp = 0; kp < 32; kp++) {
            w0[kp] = *(const ull*)&r0[2 * kp];
            w1[kp] = *(const ull*)&r1[2 * kp];
        }
    }

    const unsigned hsm_a = cvta_smem(&hsm[0][0]);
    const unsigned bar_a = cvta_smem(&mbarr[0]);

    // peer addresses (one mapa per rank; +offset stays within peer's smem)
    unsigned phsm[8], pbar[8];
#pragma unroll
    for (int r = 0; r < 8; r++) {
        phsm[r] = mapa_u32(hsm_a, r);
        pbar[r] = mapa_u32(bar_a, r);
    }

    if (tid == 0) {
        MBAR_INIT(bar_a, 1);
        MBAR_INIT(bar_a + 8, 1);
        asm volatile("fence.mbarrier_init.release.cluster;" ::: "memory");
    }
    __syncthreads();
    asm volatile("barrier.cluster.arrive.aligned;" ::: "memory");
    asm volatile("barrier.cluster.wait.aligned;" ::: "memory");

    const int ob = tid >> 6;     // owned output: batch b0+ob, col j0+oj
    const int oj = tid & 63;
    const int gb = b0 + ob, gj = j0 + oj;
    const unsigned my_off = (unsigned)(ob * Hh + j0 + oj) * 4u;  // byte off in buf
    const bool sender = (tid & 1) == 0;

    // ---- expect + broadcast h0 into buffer 0 of all peers ----
    if (tid == 0) MBAR_EXPECT_TX(bar_a, 8192);
    {
        float v = h0l[(size_t)gb * Hh + gj];
        float vn = __shfl_xor_sync(0xffffffffu, v, 1);
        if (sender) {
            ull pk; PACK2(pk, v, vn);
#pragma unroll
            for (int r = 0; r < 8; r++)
                st_async_b64(phsm[r] + my_off, pk, pbar[r]);
        }
    }

    unsigned par0 = 0, par1 = 0;

    for (int t = 0; t < Tt; t++) {
        // prefetch this thread's pre value
        size_t gidx = (size_t)t * Bb * Hh + (size_t)gb * Hh + gj;
        float pre = act[gidx];

        // post expectation for h[t+1] on the other buffer's barrier
        if (tid == 0 && t < Tt - 1)
            MBAR_EXPECT_TX(bar_a + (((t + 1) & 1) << 3), 8192);

        // wait for full h[t] tile (8 producers x 1KB delivered via st.async)
        if ((t & 1) == 0) { MBAR_WAIT_CLUSTER(bar_a, par0); par0 ^= 1; }
        else              { MBAR_WAIT_CLUSTER(bar_a + 8, par1); par1 ^= 1; }

        const float* hb = &hsm[t & 1][0];

        // ---- packed FFMA2 GEMM slice: 4b x 2j x 64k per thread ----
        ull a00 = 0, a01 = 0, a10 = 0, a11 = 0;
        ull a20 = 0, a21 = 0, a30 = 0, a31 = 0;
#pragma unroll
        for (int kp = 0; kp < 32; kp++) {
            ull wa = w0[kp], wb = w1[kp];
            ull hb0 = *(const ull*)&hb[0 * Hh + kbase + 2 * kp];
            ull hb1 = *(const ull*)&hb[1 * Hh + kbase + 2 * kp];
            ull hb2 = *(const ull*)&hb[2 * Hh + kbase + 2 * kp];
            ull hb3 = *(const ull*)&hb[3 * Hh + kbase + 2 * kp];
            FMA2(a00, wa, hb0); FMA2(a01, wb, hb0);
            FMA2(a10, wa, hb1); FMA2(a11, wb, hb1);
            FMA2(a20, wa, hb2); FMA2(a21, wb, hb2);
            FMA2(a30, wa, hb3); FMA2(a31, wb, hb3);
        }

        __syncthreads();   // previous step's red reads are done

        {
            float lo, hi, s0, s1;
            float* rp = &red[ks * 256 + 2 * jq];
            UNPK(lo, hi, a00); s0 = lo + hi; UNPK(lo, hi, a01); s1 = lo + hi;
            *(float2*)&rp[0 * 64] = make_float2(s0, s1);
            UNPK(lo, hi, a10); s0 = lo + hi; UNPK(lo, hi, a11); s1 = lo + hi;
            *(float2*)&rp[1 * 64] = make_float2(s0, s1);
            UNPK(lo, hi, a20); s0 = lo + hi; UNPK(lo, hi, a21); s1 = lo + hi;
            *(float2*)&rp[2 * 64] = make_float2(s0, s1);
            UNPK(lo, hi, a30); s0 = lo + hi; UNPK(lo, hi, a31); s1 = lo + hi;
            *(float2*)&rp[3 * 64] = make_float2(s0, s1);
        }
        __syncthreads();

        float s = 0.f;
#pragma unroll
        for (int q = 0; q < 8; q++) s += red[q * 256 + tid];

        float v = tanhf(s + pre);
        act[gidx] = v;                                   // ys in place

        if (t == Tt - 1) {
            hout[(size_t)gb * Hh + gj] = v;              // final hidden
        } else {
            // push h[t+1] tile into all 8 peers' other buffer
            float vn = __shfl_xor_sync(0xffffffffu, v, 1);
            if (sender) {
                ull pk; PACK2(pk, v, vn);
                unsigned boff = ((unsigned)((t + 1) & 1)) * 8192u;
                unsigned moff = ((unsigned)((t + 1) & 1)) << 3;
#pragma unroll
                for (int r = 0; r < 8; r++)
                    st_async_b64(phsm[r] + boff + my_off, pk, pbar[r] + moff);
            }
        }
    }

    // no peer may exit while another could still address its smem
    asm volatile("barrier.cluster.arrive.aligned;" ::: "memory");
    asm volatile("barrier.cluster.wait.aligned;" ::: "memory");
}

// ---------------- launch ----------------------------------------------------
extern "C" void kernel_launch(void* const* d_in, const int* in_sizes, int n_in,
                              void* d_out, int out_size)
{
    (void)in_sizes; (void)n_in; (void)out_size;
    const float* x     = (const float*)d_in[0];   // [T,B,IN]
    const float* h0    = (const float*)d_in[1];   // [L,B,H]
    const float* W_ih0 = (const float*)d_in[2];   // [H,IN]
    const float* W_ihr = (const float*)d_in[3];   // [L-1,H,H]
    const float* W_hh  = (const float*)d_in[4];   // [L,H,H]
    const float* b_ih  = (const float*)d_in[5];   // [L,H]
    const float* b_hh  = (const float*)d_in[6];   // [L,H]
    const float* lin_W = (const float*)d_in[7];   // [OUT,H]
    const float* lin_b = (const float*)d_in[8];   // [OUT]

    float* out   = (float*)d_out;                       // [T,B,OUT]
    float* h_out = out + (size_t)Tt * Bb * OUTN;        // [L,B,H]

    float *bufA, *bufB;
    cudaGetSymbolAddress((void**)&bufA, g_bufA);
    cudaGetSymbolAddress((void**)&bufB, g_bufB);

    dim3 blk(256);
    const int MB = (Tt * Bb) / 128;     // 256 M-blocks

    // layer 0
    sgemm_bias<INN><<<dim3(Hh / 64, MB), blk>>>(x, W_ih0, b_ih, b_hh, bufA, Hh);
    rnn_scan<<<128, blk>>>(bufA, W_hh, h0, h_out);

    // layer 1
    sgemm_bias<Hh><<<dim3(Hh / 64, MB), blk>>>(bufA, W_ihr, b_ih + Hh, b_hh + Hh,
                                               bufB, Hh);
    rnn_scan<<<128, blk>>>(bufB, W_hh + Hh * Hh, h0 + Bb * Hh, h_out + Bb * Hh);

    // layer 2
    sgemm_bias<Hh><<<dim3(Hh / 64, MB), blk>>>(bufB, W_ihr + Hh * Hh,
                                               b_ih + 2 * Hh, b_hh + 2 * Hh,
                                               bufA, Hh);
    rnn_scan<<<128, blk>>>(bufA, W_hh + 2 * Hh * Hh, h0 + 2 * Bb * Hh,
                           h_out + 2 * Bb * Hh);

    // final linear: [32768,512] @ [128,512]^T + lin_b -> d_out
    sgemm_bias<Hh><<<dim3(OUTN / 64, MB), blk>>>(bufA, lin_W, lin_b, nullptr,
                                                 out, OUTN);
}

// round 6
// speedup vs baseline: 1.1540x; 1.1540x over previous
#include <cuda_runtime.h>
#include <math.h>

#define Tt   512
#define Bb   64
#define INN  128
#define Hh   512
#define Ll   3
#define OUTN 128

// ---------------- scratch (device globals: no runtime allocation) ----------
__device__ float g_bufA[Tt * Bb * Hh];   // 64 MB activation ping
__device__ float g_bufB[Tt * Bb * Hh];   // 64 MB activation pong

// ---------------- packed fp32x2 helpers (B300 FFMA2 path) ------------------
typedef unsigned long long ull;
#define FMA2(d, a, b) asm("fma.rn.f32x2 %0, %1, %2, %0;" : "+l"(d) : "l"(a), "l"(b))
#define UNPK(lo, hi, p) asm("mov.b64 {%0, %1}, %2;" : "=f"(lo), "=f"(hi) : "l"(p))

__device__ __forceinline__ unsigned cvta_smem(const void* p) {
    unsigned a;
    asm("{ .reg .u64 t; cvta.to.shared.u64 t, %1; cvt.u32.u64 %0, t; }"
        : "=r"(a) : "l"(p));
    return a;
}
__device__ __forceinline__ unsigned mapa_u32(unsigned addr, unsigned rank) {
    unsigned r;
    asm("mapa.shared::cluster.u32 %0, %1, %2;" : "=r"(r) : "r"(addr), "r"(rank));
    return r;
}
// bulk smem -> peer smem copy, tx-accounted on the PEER's mbarrier
__device__ __forceinline__ void bulk_s2c(unsigned dst, unsigned src,
                                         unsigned bytes, unsigned rbar) {
    asm volatile(
        "cp.async.bulk.shared::cluster.shared::cta.mbarrier::complete_tx::bytes "
        "[%0], [%1], %2, [%3];"
        :: "r"(dst), "r"(src), "r"(bytes), "r"(rbar) : "memory");
}
#define MBAR_INIT(a, n) \
    asm volatile("mbarrier.init.shared.b64 [%0], %1;" :: "r"(a), "r"(n) : "memory")
#define MBAR_EXPECT_TX(a, tx) \
    asm volatile("mbarrier.arrive.expect_tx.shared.b64 _, [%0], %1;" \
                 :: "r"(a), "r"(tx) : "memory")
#define MBAR_WAIT_CLUSTER(a, ph) do {                                          \
    unsigned _dn;                                                              \
    asm volatile("{\n\t.reg .pred p;\n\t"                                      \
        "mbarrier.try_wait.parity.acquire.cluster.shared::cta.b64 p, [%1], %2;\n\t" \
        "selp.b32 %0, 1, 0, p;\n\t}"                                           \
        : "=r"(_dn) : "r"(a), "r"(ph) : "memory");                             \
    while (!_dn) {                                                             \
        asm volatile("{\n\t.reg .pred p;\n\t"                                  \
            "mbarrier.try_wait.parity.acquire.cluster.shared::cta.b64 p, [%1], %2, 0x989680;\n\t" \
            "selp.b32 %0, 1, 0, p;\n\t}"                                       \
            : "=r"(_dn) : "r"(a), "r"(ph) : "memory");                         \
    }                                                                          \
} while (0)

// ---------------- SGEMM: Y[M,N] = X[M,K] @ W[N,K]^T + b1(+b2) --------------
template <int K>
__global__ __launch_bounds__(256, 2) void sgemm_bias(
    const float* __restrict__ X, const float* __restrict__ W,
    const float* __restrict__ b1, const float* __restrict__ b2,
    float* __restrict__ Y, int N)
{
    constexpr int BM = 128, BN = 64, BK = 32, SA = BK + 2;
    __shared__ float Asm[BM * SA];
    __shared__ float Wsm[BN * SA];

    const int tid = threadIdx.x;
    const int r = tid >> 4;
    const int c = tid & 15;
    const int m0 = blockIdx.y * BM;
    const int n0 = blockIdx.x * BN;

    ull acc[8][4];
#pragma unroll
    for (int i = 0; i < 8; i++)
#pragma unroll
        for (int j = 0; j < 4; j++) acc[i][j] = 0ull;

    for (int k0 = 0; k0 < K; k0 += BK) {
#pragma unroll
        for (int i = 0; i < 4; i++) {
            int f = tid + i * 256;
            int m = f >> 3, kq = f & 7;
            float4 v = *(const float4*)&X[(size_t)(m0 + m) * K + k0 + kq * 4];
            float* d = &Asm[m * SA + kq * 4];
            *(float2*)&d[0] = make_float2(v.x, v.y);
            *(float2*)&d[2] = make_float2(v.z, v.w);
        }
#pragma unroll
        for (int i = 0; i < 2; i++) {
            int f = tid + i * 256;
            int n = f >> 3, kq = f & 7;
            float4 v = *(const float4*)&W[(size_t)(n0 + n) * K + k0 + kq * 4];
            float* d = &Wsm[n * SA + kq * 4];
            *(float2*)&d[0] = make_float2(v.x, v.y);
            *(float2*)&d[2] = make_float2(v.z, v.w);
        }
        __syncthreads();

#pragma unroll
        for (int kp = 0; kp < BK / 2; kp++) {
            ull a[8], b[4];
#pragma unroll
            for (int i = 0; i < 8; i++)
                a[i] = *(const ull*)&Asm[(r * 8 + i) * SA + 2 * kp];
#pragma unroll
            for (int j = 0; j < 4; j++)
                b[j] = *(const ull*)&Wsm[(j * 16 + c) * SA + 2 * kp];
#pragma unroll
            for (int i = 0; i < 8; i++)
#pragma unroll
                for (int j = 0; j < 4; j++) FMA2(acc[i][j], a[i], b[j]);
        }
        __syncthreads();
    }

#pragma unroll
    for (int i = 0; i < 8; i++) {
        int m = m0 + r * 8 + i;
#pragma unroll
        for (int j = 0; j < 4; j++) {
            int n = n0 + j * 16 + c;
            float lo, hi;
            UNPK(lo, hi, acc[i][j]);
            float bias = b1[n];
            if (b2) bias += b2[n];
            Y[(size_t)m * N + n] = lo + hi + bias;
        }
    }
}

// ---------------- recurrent scan (8-CTA DSMEM cluster per batch group) -----
// 128 CTAs = 16 clusters (batch groups, 4 b each) x 8 ranks (j-groups, 64 j).
// Exchange: producer stages its 1KB h-tile locally, then 8 threads each issue
// ONE cp.async.bulk to a peer's rank-major recv buffer (tx on peer mbarrier).
// 8 messages/CTA/step (vs 1024 st.async in R4) -> no mbarrier tx serialization.
// Recv layout hsm[buf][rank][b][64]: rank slice contiguous; FFMA k-range of
// warp ks reads exactly rank ks's slice (warp-broadcast LDS, conflict-free).
__global__ __launch_bounds__(256) __cluster_dims__(8, 1, 1)
void rnn_scan(
    float* __restrict__ act,         // [T,B,H] pre -> overwritten with ys
    const float* __restrict__ Whh,   // [H,H] row-major (j,k)
    const float* __restrict__ h0l,   // [B,H]
    float* __restrict__ hout)        // [B,H] final hidden
{
    __shared__ __align__(16) float hsm[2][2048];   // [buf][rank*256 + b*64 + j]
    __shared__ __align__(16) float sbuf[2][256];   // staging [buf][b*64 + j]
    __shared__ __align__(16) float red[8 * 256];   // k-split reduction
    __shared__ __align__(8)  ull  mbarr[2];

    const int tid = threadIdx.x;
    const int jq  = tid & 31;        // 0..31 -> 2 j each
    const int ks  = tid >> 5;        // 0..7  -> 64 k each (== source rank)
    const int jg  = blockIdx.x & 7;  // cluster rank
    const int bg  = blockIdx.x >> 3;
    const int j0  = jg * 64;
    const int b0  = bg * 4;
    const int kbase = ks * 64;

    // ---- persistent W slice in registers ----
    ull w0[32], w1[32];
    {
        const float* r0 = &Whh[(size_t)(j0 + 2 * jq + 0) * Hh + kbase];
        const float* r1 = &Whh[(size_t)(j0 + 2 * jq + 1) * Hh + kbase];
#pragma unroll
        for (int kp = 0; kp < 32; kp++) {
            w0[kp] = *(const ull*)&r0[2 * kp];
            w1[kp] = *(const ull*)&r1[2 * kp];
        }
    }

    const unsigned hsm_a  = cvta_smem(&hsm[0][0]);
    const unsigned sbuf_a = cvta_smem(&sbuf[0][0]);
    const unsigned bar_a  = cvta_smem(&mbarr[0]);

    // peer base addresses for the 8 ranks (tid r sends to rank r)
    unsigned my_dst = 0, my_bar = 0;
    if (tid < 8) {
        my_dst = mapa_u32(hsm_a, tid) + (unsigned)jg * 1024u;  // our slot in peer
        my_bar = mapa_u32(bar_a, tid);
    }

    if (tid == 0) {
        MBAR_INIT(bar_a, 1);
        MBAR_INIT(bar_a + 8, 1);
        asm volatile("fence.mbarrier_init.release.cluster;" ::: "memory");
    }
    __syncthreads();
    asm volatile("barrier.cluster.arrive.aligned;" ::: "memory");
    asm volatile("barrier.cluster.wait.aligned;" ::: "memory");

    const int ob = tid >> 6;     // owned output: batch b0+ob, col j0+oj
    const int oj = tid & 63;
    const int gb = b0 + ob, gj = j0 + oj;

    // ---- broadcast h0 into buffer 0 of all peers (bulk path) ----
    if (tid == 0) MBAR_EXPECT_TX(bar_a, 8192);
    sbuf[0][tid] = h0l[(size_t)gb * Hh + gj];
    __syncthreads();
    if (tid < 8) {
        asm volatile("fence.proxy.async.shared::cta;" ::: "memory");
        bulk_s2c(my_dst, sbuf_a, 1024u, my_bar);
    }

    unsigned par0 = 0, par1 = 0;

    for (int t = 0; t < Tt; t++) {
        // prefetch this thread's pre value
        size_t gidx = (size_t)t * Bb * Hh + (size_t)gb * Hh + gj;
        float pre = act[gidx];

        // post expectation for h[t+1] on the other buffer's barrier
        if (tid == 0 && t < Tt - 1)
            MBAR_EXPECT_TX(bar_a + (((t + 1) & 1) << 3), 8192);

        // wait for full h[t] tile (8 x 1KB bulk deliveries)
        if ((t & 1) == 0) { MBAR_WAIT_CLUSTER(bar_a, par0); par0 ^= 1; }
        else              { MBAR_WAIT_CLUSTER(bar_a + 8, par1); par1 ^= 1; }

        const float* hb = &hsm[t & 1][ks * 256];   // this warp's rank slice

        // ---- packed FFMA2 GEMM slice: 4b x 2j x 64k per thread ----
        ull a00 = 0, a01 = 0, a10 = 0, a11 = 0;
        ull a20 = 0, a21 = 0, a30 = 0, a31 = 0;
#pragma unroll
        for (int kp = 0; kp < 32; kp++) {
            ull wa = w0[kp], wb = w1[kp];
            ull hb0 = *(const ull*)&hb[0 * 64 + 2 * kp];
            ull hb1 = *(const ull*)&hb[1 * 64 + 2 * kp];
            ull hb2 = *(const ull*)&hb[2 * 64 + 2 * kp];
            ull hb3 = *(const ull*)&hb[3 * 64 + 2 * kp];
            FMA2(a00, wa, hb0); FMA2(a01, wb, hb0);
            FMA2(a10, wa, hb1); FMA2(a11, wb, hb1);
            FMA2(a20, wa, hb2); FMA2(a21, wb, hb2);
            FMA2(a30, wa, hb3); FMA2(a31, wb, hb3);
        }

        __syncthreads();   // previous step's red reads are done

        {
            float lo, hi, s0, s1;
            float* rp = &red[ks * 256 + 2 * jq];
            UNPK(lo, hi, a00); s0 = lo + hi; UNPK(lo, hi, a01); s1 = lo + hi;
            *(float2*)&rp[0 * 64] = make_float2(s0, s1);
            UNPK(lo, hi, a10); s0 = lo + hi; UNPK(lo, hi, a11); s1 = lo + hi;
            *(float2*)&rp[1 * 64] = make_float2(s0, s1);
            UNPK(lo, hi, a20); s0 = lo + hi; UNPK(lo, hi, a21); s1 = lo + hi;
            *(float2*)&rp[2 * 64] = make_float2(s0, s1);
            UNPK(lo, hi, a30); s0 = lo + hi; UNPK(lo, hi, a31); s1 = lo + hi;
            *(float2*)&rp[3 * 64] = make_float2(s0, s1);
        }
        __syncthreads();

        float s = 0.f;
#pragma unroll
        for (int q = 0; q < 8; q++) s += red[q * 256 + tid];

        float v = tanhf(s + pre);

        if (t < Tt - 1) {
            // stage + bulk-send h[t+1] FIRST (it's the cross-CTA critical path)
            int nb = (t + 1) & 1;
            sbuf[nb][tid] = v;
            __syncthreads();
            if (tid < 8) {
                asm volatile("fence.proxy.async.shared::cta;" ::: "memory");
                bulk_s2c(my_dst + (unsigned)nb * 8192u, sbuf_a + (unsigned)nb * 1024u,
                         1024u, my_bar + ((unsigned)nb << 3));
            }
        } else {
            hout[(size_t)gb * Hh + gj] = v;          // final hidden
        }
        act[gidx] = v;                               // ys store off critical path
    }

    // no peer may exit while another could still address its smem
    asm volatile("barrier.cluster.arrive.aligned;" ::: "memory");
    asm volatile("barrier.cluster.wait.aligned;" ::: "memory");
}

// ---------------- launch ----------------------------------------------------
extern "C" void kernel_launch(void* const* d_in, const int* in_sizes, int n_in,
                              void* d_out, int out_size)
{
    (void)in_sizes; (void)n_in; (void)out_size;
    const float* x     = (const float*)d_in[0];   // [T,B,IN]
    const float* h0    = (const float*)d_in[1];   // [L,B,H]
    const float* W_ih0 = (const float*)d_in[2];   // [H,IN]
    const float* W_ihr = (const float*)d_in[3];   // [L-1,H,H]
    const float* W_hh  = (const float*)d_in[4];   // [L,H,H]
    const float* b_ih  = (const float*)d_in[5];   // [L,H]
    const float* b_hh  = (const float*)d_in[6];   // [L,H]
    const float* lin_W = (const float*)d_in[7];   // [OUT,H]
    const float* lin_b = (const float*)d_in[8];   // [OUT]

    float* out   = (float*)d_out;                       // [T,B,OUT]
    float* h_out = out + (size_t)Tt * Bb * OUTN;        // [L,B,H]

    float *bufA, *bufB;
    cudaGetSymbolAddress((void**)&bufA, g_bufA);
    cudaGetSymbolAddress((void**)&bufB, g_bufB);

    dim3 blk(256);
    const int MB = (Tt * Bb) / 128;     // 256 M-blocks

    // layer 0
    sgemm_bias<INN><<<dim3(Hh / 64, MB), blk>>>(x, W_ih0, b_ih, b_hh, bufA, Hh);
    rnn_scan<<<128, blk>>>(bufA, W_hh, h0, h_out);

    // layer 1
    sgemm_bias<Hh><<<dim3(Hh / 64, MB), blk>>>(bufA, W_ihr, b_ih + Hh, b_hh + Hh,
                                               bufB, Hh);
    rnn_scan<<<128, blk>>>(bufB, W_hh + Hh * Hh, h0 + Bb * Hh, h_out + Bb * Hh);

    // layer 2
    sgemm_bias<Hh><<<dim3(Hh / 64, MB), blk>>>(bufB, W_ihr + Hh * Hh,
                                               b_ih + 2 * Hh, b_hh + 2 * Hh,
                                               bufA, Hh);
    rnn_scan<<<128, blk>>>(bufA, W_hh + 2 * Hh * Hh, h0 + 2 * Bb * Hh,
                           h_out + 2 * Bb * Hh);

    // final linear: [32768,512] @ [128,512]^T + lin_b -> d_out
    sgemm_bias<Hh><<<dim3(OUTN / 64, MB), blk>>>(bufA, lin_W, lin_b, nullptr,
                                                 out, OUTN);
}

// round 7
// speedup vs baseline: 1.2087x; 1.0474x over previous
#include <cuda_runtime.h>
#include <math.h>

#define Tt   512
#define Bb   64
#define INN  128
#define Hh   512
#define Ll   3
#define OUTN 128

// ---------------- scratch (device globals: no runtime allocation) ----------
__device__ float g_bufA[Tt * Bb * Hh];   // 64 MB activation ping
__device__ float g_bufB[Tt * Bb * Hh];   // 64 MB activation pong

// ---------------- packed fp32x2 helpers (B300 FFMA2 path) ------------------
typedef unsigned long long ull;
#define FMA2(d, a, b) asm("fma.rn.f32x2 %0, %1, %2, %0;" : "+l"(d) : "l"(a), "l"(b))
#define UNPK(lo, hi, p) asm("mov.b64 {%0, %1}, %2;" : "=f"(lo), "=f"(hi) : "l"(p))

__device__ __forceinline__ unsigned cvta_smem(const void* p) {
    unsigned a;
    asm("{ .reg .u64 t; cvta.to.shared.u64 t, %1; cvt.u32.u64 %0, t; }"
        : "=r"(a) : "l"(p));
    return a;
}
__device__ __forceinline__ unsigned mapa_u32(unsigned addr, unsigned rank) {
    unsigned r;
    asm("mapa.shared::cluster.u32 %0, %1, %2;" : "=r"(r) : "r"(addr), "r"(rank));
    return r;
}
// bulk smem -> peer smem copy, tx-accounted on the PEER's mbarrier
__device__ __forceinline__ void bulk_s2c(unsigned dst, unsigned src,
                                         unsigned bytes, unsigned rbar) {
    asm volatile(
        "cp.async.bulk.shared::cluster.shared::cta.mbarrier::complete_tx::bytes "
        "[%0], [%1], %2, [%3];"
        :: "r"(dst), "r"(src), "r"(bytes), "r"(rbar) : "memory");
}
#define MBAR_INIT(a, n) \
    asm volatile("mbarrier.init.shared.b64 [%0], %1;" :: "r"(a), "r"(n) : "memory")
#define MBAR_EXPECT_TX(a, tx) \
    asm volatile("mbarrier.arrive.expect_tx.shared.b64 _, [%0], %1;" \
                 :: "r"(a), "r"(tx) : "memory")
#define MBAR_WAIT_CLUSTER(a, ph) do {                                          \
    unsigned _dn;                                                              \
    asm volatile("{\n\t.reg .pred p;\n\t"                                      \
        "mbarrier.try_wait.parity.acquire.cluster.shared::cta.b64 p, [%1], %2;\n\t" \
        "selp.b32 %0, 1, 0, p;\n\t}"                                           \
        : "=r"(_dn) : "r"(a), "r"(ph) : "memory");                             \
    while (!_dn) {                                                             \
        asm volatile("{\n\t.reg .pred p;\n\t"                                  \
            "mbarrier.try_wait.parity.acquire.cluster.shared::cta.b64 p, [%1], %2, 0x989680;\n\t" \
            "selp.b32 %0, 1, 0, p;\n\t}"                                       \
            : "=r"(_dn) : "r"(a), "r"(ph) : "memory");                         \
    }                                                                          \
} while (0)

// ---------------- SGEMM: Y[M,N] = X[M,K] @ W[N,K]^T + b1(+b2) --------------
template <int K>
__global__ __launch_bounds__(256, 2) void sgemm_bias(
    const float* __restrict__ X, const float* __restrict__ W,
    const float* __restrict__ b1, const float* __restrict__ b2,
    float* __restrict__ Y, int N)
{
    constexpr int BM = 128, BN = 64, BK = 32, SA = BK + 2;
    __shared__ float Asm[BM * SA];
    __shared__ float Wsm[BN * SA];

    const int tid = threadIdx.x;
    const int r = tid >> 4;
    const int c = tid & 15;
    const int m0 = blockIdx.y * BM;
    const int n0 = blockIdx.x * BN;

    ull acc[8][4];
#pragma unroll
    for (int i = 0; i < 8; i++)
#pragma unroll
        for (int j = 0; j < 4; j++) acc[i][j] = 0ull;

    for (int k0 = 0; k0 < K; k0 += BK) {
#pragma unroll
        for (int i = 0; i < 4; i++) {
            int f = tid + i * 256;
            int m = f >> 3, kq = f & 7;
            float4 v = *(const float4*)&X[(size_t)(m0 + m) * K + k0 + kq * 4];
            float* d = &Asm[m * SA + kq * 4];
            *(float2*)&d[0] = make_float2(v.x, v.y);
            *(float2*)&d[2] = make_float2(v.z, v.w);
        }
#pragma unroll
        for (int i = 0; i < 2; i++) {
            int f = tid + i * 256;
            int n = f >> 3, kq = f & 7;
            float4 v = *(const float4*)&W[(size_t)(n0 + n) * K + k0 + kq * 4];
            float* d = &Wsm[n * SA + kq * 4];
            *(float2*)&d[0] = make_float2(v.x, v.y);
            *(float2*)&d[2] = make_float2(v.z, v.w);
        }
        __syncthreads();

#pragma unroll
        for (int kp = 0; kp < BK / 2; kp++) {
            ull a[8], b[4];
#pragma unroll
            for (int i = 0; i < 8; i++)
                a[i] = *(const ull*)&Asm[(r * 8 + i) * SA + 2 * kp];
#pragma unroll
            for (int j = 0; j < 4; j++)
                b[j] = *(const ull*)&Wsm[(j * 16 + c) * SA + 2 * kp];
#pragma unroll
            for (int i = 0; i < 8; i++)
#pragma unroll
                for (int j = 0; j < 4; j++) FMA2(acc[i][j], a[i], b[j]);
        }
        __syncthreads();
    }

#pragma unroll
    for (int i = 0; i < 8; i++) {
        int m = m0 + r * 8 + i;
#pragma unroll
        for (int j = 0; j < 4; j++) {
            int n = n0 + j * 16 + c;
            float lo, hi;
            UNPK(lo, hi, acc[i][j]);
            float bias = b1[n];
            if (b2) bias += b2[n];
            Y[(size_t)m * N + n] = lo + hi + bias;
        }
    }
}

// ---------------- recurrent scan (8-CTA cluster, warp-autonomous comm) -----
// 128 CTAs = 16 clusters (4 b each) x 8 ranks (64 j each).
// Consumer warp w reads ONLY rank w's 1KB slice -> per-rank mbarriers [buf][rank],
// each fed by 8 x 128B cp.async.bulk (one per producer warp). No CTA-wide wait,
// no consumer loads, no producer threadfence. One __syncthreads per step (red).
__global__ __launch_bounds__(256) __cluster_dims__(8, 1, 1)
void rnn_scan(
    float* __restrict__ act,         // [T,B,H] pre -> overwritten with ys
    const float* __restrict__ Whh,   // [H,H] row-major (j,k)
    const float* __restrict__ h0l,   // [B,H]
    float* __restrict__ hout)        // [B,H] final hidden
{
    __shared__ __align__(16) float hsm[2][2048];   // [buf][rank*256 + b*64 + kk]
    __shared__ __align__(16) float red[2][2048];   // [buf][ks*256 + b*64 + j]
    __shared__ __align__(16) float sbuf[2][256];   // [buf][w*32 + lane]
    __shared__ __align__(8)  ull  mbarr[16];       // [buf*8 + rank]

    const int tid  = threadIdx.x;
    const int lane = tid & 31;
    const int w    = tid >> 5;       // warp = k-slice = consumed producer rank
    const int jg   = blockIdx.x & 7; // cluster rank
    const int bg   = blockIdx.x >> 3;
    const int j0   = jg * 64;
    const int b0   = bg * 4;
    const int kbase = w * 64;

    // ---- persistent W slice in registers: j pair (j0+2*lane, +1), k-slice w ----
    ull w0[32], w1[32];
    {
        const float* r0 = &Whh[(size_t)(j0 + 2 * lane + 0) * Hh + kbase];
        const float* r1 = &Whh[(size_t)(j0 + 2 * lane + 1) * Hh + kbase];
#pragma unroll
        for (int kp = 0; kp < 32; kp++) {
            w0[kp] = *(const ull*)&r0[2 * kp];
            w1[kp] = *(const ull*)&r1[2 * kp];
        }
    }

    const unsigned hsm_a  = cvta_smem(&hsm[0][0]);
    const unsigned sbuf_a = cvta_smem(&sbuf[0][0]);
    const unsigned bar_a  = cvta_smem(&mbarr[0]);

    // per-lane peer addresses (lane r sends this warp's 128B chunk to rank r)
    unsigned peer_hsm = 0, peer_bar = 0;
    if (lane < 8) {
        peer_hsm = mapa_u32(hsm_a, lane) + (unsigned)(jg * 1024 + w * 128);
        peer_bar = mapa_u32(bar_a, lane) + (unsigned)(jg * 8);
    }

    if (tid < 16) MBAR_INIT(bar_a + tid * 8, 1);
    if (tid == 0)
        asm volatile("fence.mbarrier_init.release.cluster;" ::: "memory");

    // ---- bootstrap: warp w loads its own h0 k-slice locally (no comm) ----
#pragma unroll
    for (int b = 0; b < 4; b++) {
        hsm[0][w * 256 + b * 64 + lane]      = h0l[(size_t)(b0 + b) * Hh + kbase + lane];
        hsm[0][w * 256 + b * 64 + 32 + lane] = h0l[(size_t)(b0 + b) * Hh + kbase + 32 + lane];
    }
    __syncthreads();
    asm volatile("barrier.cluster.arrive.aligned;" ::: "memory");
    asm volatile("barrier.cluster.wait.aligned;" ::: "memory");

    // outputs: warp w owns o = 32w + lane  (contiguous 128B chunk)
    const int o  = 32 * w + lane;
    const int ob = o >> 6, oj = o & 63;
    const int gb = b0 + ob, gj = j0 + oj;

    unsigned par0 = 0, par1 = 0;

    for (int t = 0; t < Tt; t++) {
        const int buf = t & 1, nb = (t + 1) & 1;
        size_t gidx = (size_t)t * Bb * Hh + (size_t)gb * Hh + gj;
        float pre = act[gidx];                      // overlapped with wait/FFMA

        // post expectation for h[t+1] on this warp's next-buffer barrier
        if (t < Tt - 1 && lane == 0)
            MBAR_EXPECT_TX(bar_a + (nb * 8 + w) * 8, 1024);

        // per-warp wait: only rank w's slice is needed (t=0 loaded locally)
        if (t > 0) {
            if (buf == 0) { MBAR_WAIT_CLUSTER(bar_a + (0 * 8 + w) * 8, par0); par0 ^= 1; }
            else          { MBAR_WAIT_CLUSTER(bar_a + (1 * 8 + w) * 8, par1); par1 ^= 1; }
        }

        const float* hb = &hsm[buf][w * 256];

        // ---- packed FFMA2 GEMM slice: 4b x 2j x 64k per thread ----
        ull a00 = 0, a01 = 0, a10 = 0, a11 = 0;
        ull a20 = 0, a21 = 0, a30 = 0, a31 = 0;
#pragma unroll
        for (int kp = 0; kp < 32; kp++) {
            ull wa = w0[kp], wb = w1[kp];
            ull hb0 = *(const ull*)&hb[0 * 64 + 2 * kp];
            ull hb1 = *(const ull*)&hb[1 * 64 + 2 * kp];
            ull hb2 = *(const ull*)&hb[2 * 64 + 2 * kp];
            ull hb3 = *(const ull*)&hb[3 * 64 + 2 * kp];
            FMA2(a00, wa, hb0); FMA2(a01, wb, hb0);
            FMA2(a10, wa, hb1); FMA2(a11, wb, hb1);
            FMA2(a20, wa, hb2); FMA2(a21, wb, hb2);
            FMA2(a30, wa, hb3); FMA2(a31, wb, hb3);
        }

        // ---- k-split partials (double-buffered red) ----
        {
            float lo, hi, s0, s1;
            float* rp = &red[buf][w * 256 + 2 * lane];
            UNPK(lo, hi, a00); s0 = lo + hi; UNPK(lo, hi, a01); s1 = lo + hi;
            *(float2*)&rp[0 * 64] = make_float2(s0, s1);
            UNPK(lo, hi, a10); s0 = lo + hi; UNPK(lo, hi, a11); s1 = lo + hi;
            *(float2*)&rp[1 * 64] = make_float2(s0, s1);
            UNPK(lo, hi, a20); s0 = lo + hi; UNPK(lo, hi, a21); s1 = lo + hi;
            *(float2*)&rp[2 * 64] = make_float2(s0, s1);
            UNPK(lo, hi, a30); s0 = lo + hi; UNPK(lo, hi, a31); s1 = lo + hi;
            *(float2*)&rp[3 * 64] = make_float2(s0, s1);
        }
        __syncthreads();     // the ONE CTA sync per step

        // ---- warp-autonomous reduce + tanh + send of owned 32 outputs ----
        float s = 0.f;
#pragma unroll
        for (int q = 0; q < 8; q++) s += red[buf][q * 256 + o];
        float v = tanhf(s + pre);

        if (t < Tt - 1) {
            sbuf[nb][w * 32 + lane] = v;
            __syncwarp();
            if (lane < 8) {
                asm volatile("fence.proxy.async.shared::cta;" ::: "memory");
                bulk_s2c(peer_hsm + (unsigned)nb * 8192u,
                         sbuf_a + (unsigned)(nb * 1024 + w * 128),
                         128u, peer_bar + (unsigned)nb * 64u);
            }
        } else {
            hout[(size_t)gb * Hh + gj] = v;          // final hidden
        }
        act[gidx] = v;                               // ys store off critical path
    }

    // no peer may exit while another could still address its smem
    asm volatile("barrier.cluster.arrive.aligned;" ::: "memory");
    asm volatile("barrier.cluster.wait.aligned;" ::: "memory");
}

// ---------------- launch ----------------------------------------------------
extern "C" void kernel_launch(void* const* d_in, const int* in_sizes, int n_in,
                              void* d_out, int out_size)
{
    (void)in_sizes; (void)n_in; (void)out_size;
    const float* x     = (const float*)d_in[0];   // [T,B,IN]
    const float* h0    = (const float*)d_in[1];   // [L,B,H]
    const float* W_ih0 = (const float*)d_in[2];   // [H,IN]
    const float* W_ihr = (const float*)d_in[3];   // [L-1,H,H]
    const float* W_hh  = (const float*)d_in[4];   // [L,H,H]
    const float* b_ih  = (const float*)d_in[5];   // [L,H]
    const float* b_hh  = (const float*)d_in[6];   // [L,H]
    const float* lin_W = (const float*)d_in[7];   // [OUT,H]
    const float* lin_b = (const float*)d_in[8];   // [OUT]

    float* out   = (float*)d_out;                       // [T,B,OUT]
    float* h_out = out + (size_t)Tt * Bb * OUTN;        // [L,B,H]

    float *bufA, *bufB;
    cudaGetSymbolAddress((void**)&bufA, g_bufA);
    cudaGetSymbolAddress((void**)&bufB, g_bufB);

    dim3 blk(256);
    const int MB = (Tt * Bb) / 128;     // 256 M-blocks

    // layer 0
    sgemm_bias<INN><<<dim3(Hh / 64, MB), blk>>>(x, W_ih0, b_ih, b_hh, bufA, Hh);
    rnn_scan<<<128, blk>>>(bufA, W_hh, h0, h_out);

    // layer 1
    sgemm_bias<Hh><<<dim3(Hh / 64, MB), blk>>>(bufA, W_ihr, b_ih + Hh, b_hh + Hh,
                                               bufB, Hh);
    rnn_scan<<<128, blk>>>(bufB, W_hh + Hh * Hh, h0 + Bb * Hh, h_out + Bb * Hh);

    // layer 2
    sgemm_bias<Hh><<<dim3(Hh / 64, MB), blk>>>(bufB, W_ihr + Hh * Hh,
                                               b_ih + 2 * Hh, b_hh + 2 * Hh,
                                               bufA, Hh);
    rnn_scan<<<128, blk>>>(bufA, W_hh + 2 * Hh * Hh, h0 + 2 * Bb * Hh,
                           h_out + 2 * Bb * Hh);

    // final linear: [32768,512] @ [128,512]^T + lin_b -> d_out
    sgemm_bias<Hh><<<dim3(OUTN / 64, MB), blk>>>(bufA, lin_W, lin_b, nullptr,
                                                 out, OUTN);
}

// round 8
// speedup vs baseline: 1.2399x; 1.0258x over previous
#include <cuda_runtime.h>
#include <math.h>

#define Tt   512
#define Bb   64
#define INN  128
#define Hh   512
#define Ll   3
#define OUTN 128

// ---------------- scratch (device globals: no runtime allocation) ----------
__device__ float g_bufA[Tt * Bb * Hh];   // 64 MB activation ping
__device__ float g_bufB[Tt * Bb * Hh];   // 64 MB activation pong

// ---------------- packed fp32x2 helpers (B300 FFMA2 path) ------------------
typedef unsigned long long ull;
#define FMA2(d, a, b) asm("fma.rn.f32x2 %0, %1, %2, %0;" : "+l"(d) : "l"(a), "l"(b))
#define UNPK(lo, hi, p) asm("mov.b64 {%0, %1}, %2;" : "=f"(lo), "=f"(hi) : "l"(p))

__device__ __forceinline__ unsigned cvta_smem(const void* p) {
    unsigned a;
    asm("{ .reg .u64 t; cvta.to.shared.u64 t, %1; cvt.u32.u64 %0, t; }"
        : "=r"(a) : "l"(p));
    return a;
}
__device__ __forceinline__ unsigned mapa_u32(unsigned addr, unsigned rank) {
    unsigned r;
    asm("mapa.shared::cluster.u32 %0, %1, %2;" : "=r"(r) : "r"(addr), "r"(rank));
    return r;
}
// bulk smem -> peer smem copy, tx-accounted on the PEER's mbarrier
__device__ __forceinline__ void bulk_s2c(unsigned dst, unsigned src,
                                         unsigned bytes, unsigned rbar) {
    asm volatile(
        "cp.async.bulk.shared::cluster.shared::cta.mbarrier::complete_tx::bytes "
        "[%0], [%1], %2, [%3];"
        :: "r"(dst), "r"(src), "r"(bytes), "r"(rbar) : "memory");
}
#define MBAR_INIT(a, n) \
    asm volatile("mbarrier.init.shared.b64 [%0], %1;" :: "r"(a), "r"(n) : "memory")
#define MBAR_EXPECT_TX(a, tx) \
    asm volatile("mbarrier.arrive.expect_tx.shared.b64 _, [%0], %1;" \
                 :: "r"(a), "r"(tx) : "memory")
#define MBAR_WAIT_CLUSTER(a, ph) do {                                          \
    unsigned _dn;                                                              \
    asm volatile("{\n\t.reg .pred p;\n\t"                                      \
        "mbarrier.try_wait.parity.acquire.cluster.shared::cta.b64 p, [%1], %2;\n\t" \
        "selp.b32 %0, 1, 0, p;\n\t}"                                           \
        : "=r"(_dn) : "r"(a), "r"(ph) : "memory");                             \
    while (!_dn) {                                                             \
        asm volatile("{\n\t.reg .pred p;\n\t"                                  \
            "mbarrier.try_wait.parity.acquire.cluster.shared::cta.b64 p, [%1], %2, 0x989680;\n\t" \
            "selp.b32 %0, 1, 0, p;\n\t}"                                       \
            : "=r"(_dn) : "r"(a), "r"(ph) : "memory");                         \
    }                                                                          \
} while (0)

// ---------------- SGEMM: Y[M,N] = X[M,K] @ W[N,K]^T + b1(+b2) --------------
template <int K>
__global__ __launch_bounds__(256, 2) void sgemm_bias(
    const float* __restrict__ X, const float* __restrict__ W,
    const float* __restrict__ b1, const float* __restrict__ b2,
    float* __restrict__ Y, int N)
{
    constexpr int BM = 128, BN = 64, BK = 32, SA = BK + 2;
    __shared__ float Asm[BM * SA];
    __shared__ float Wsm[BN * SA];

    const int tid = threadIdx.x;
    const int r = tid >> 4;
    const int c = tid & 15;
    const int m0 = blockIdx.y * BM;
    const int n0 = blockIdx.x * BN;

    ull acc[8][4];
#pragma unroll
    for (int i = 0; i < 8; i++)
#pragma unroll
        for (int j = 0; j < 4; j++) acc[i][j] = 0ull;

    for (int k0 = 0; k0 < K; k0 += BK) {
#pragma unroll
        for (int i = 0; i < 4; i++) {
            int f = tid + i * 256;
            int m = f >> 3, kq = f & 7;
            float4 v = *(const float4*)&X[(size_t)(m0 + m) * K + k0 + kq * 4];
            float* d = &Asm[m * SA + kq * 4];
            *(float2*)&d[0] = make_float2(v.x, v.y);
            *(float2*)&d[2] = make_float2(v.z, v.w);
        }
#pragma unroll
        for (int i = 0; i < 2; i++) {
            int f = tid + i * 256;
            int n = f >> 3, kq = f & 7;
            float4 v = *(const float4*)&W[(size_t)(n0 + n) * K + k0 + kq * 4];
            float* d = &Wsm[n * SA + kq * 4];
            *(float2*)&d[0] = make_float2(v.x, v.y);
            *(float2*)&d[2] = make_float2(v.z, v.w);
        }
        __syncthreads();

#pragma unroll
        for (int kp = 0; kp < BK / 2; kp++) {
            ull a[8], b[4];
#pragma unroll
            for (int i = 0; i < 8; i++)
                a[i] = *(const ull*)&Asm[(r * 8 + i) * SA + 2 * kp];
#pragma unroll
            for (int j = 0; j < 4; j++)
                b[j] = *(const ull*)&Wsm[(j * 16 + c) * SA + 2 * kp];
#pragma unroll
            for (int i = 0; i < 8; i++)
#pragma unroll
                for (int j = 0; j < 4; j++) FMA2(acc[i][j], a[i], b[j]);
        }
        __syncthreads();
    }

#pragma unroll
    for (int i = 0; i < 8; i++) {
        int m = m0 + r * 8 + i;
#pragma unroll
        for (int j = 0; j < 4; j++) {
            int n = n0 + j * 16 + c;
            float lo, hi;
            UNPK(lo, hi, acc[i][j]);
            float bias = b1[n];
            if (b2) bias += b2[n];
            Y[(size_t)m * N + n] = lo + hi + bias;
        }
    }
}

// ---------------- recurrent scan: partial-exchange dataflow ----------------
// 128 CTAs = 16 clusters (4 batches) x 8 ranks. Rank r owns j-slice r AND
// k-slice r (its own h chunk is next step's k-input -> h never broadcast).
// Per step, warp w computes the k-partial for rank w's 64 outputs over OUR
// 64-k slice and sends ONE 1KB bulk copy to peer w (8 msgs/CTA/step total).
// Consumer sums 8 incoming partials + pre, tanh -> own h chunk. One
// __syncthreads per step; no k-split smem reduction; W [all j][own k] in regs.
__global__ __launch_bounds__(256) __cluster_dims__(8, 1, 1)
void rnn_scan(
    float* __restrict__ act,         // [T,B,H] pre -> overwritten with ys
    const float* __restrict__ Whh,   // [H,H] row-major (j,k)
    const float* __restrict__ h0l,   // [B,H]
    float* __restrict__ hout)        // [B,H] final hidden
{
    __shared__ __align__(16) float hprt[2][8][256];  // recv partials [buf][src][b*64+j']
    __shared__ __align__(16) float sout[2][8][256];  // outgoing [buf][dest=w][b*64+j']
    __shared__ __align__(16) float hstage[2][256];   // own h chunk [buf][b*64+k']
    __shared__ __align__(8)  ull  mbarr[2];

    const int tid  = threadIdx.x;
    const int lane = tid & 31;
    const int w    = tid >> 5;       // warp = destination rank (j-block 64w..)
    const int jg   = blockIdx.x & 7; // cluster rank: owns j & k slice jg
    const int bg   = blockIdx.x >> 3;
    const int b0   = bg * 4;

    // ---- persistent W slice in registers ----
    // warp w, lane l: rows j = 64w + 2l (+1), cols k = [64*jg, 64*jg+64)
    ull w0[32], w1[32];
    {
        const float* r0 = &Whh[(size_t)(64 * w + 2 * lane + 0) * Hh + 64 * jg];
        const float* r1 = &Whh[(size_t)(64 * w + 2 * lane + 1) * Hh + 64 * jg];
#pragma unroll
        for (int kp = 0; kp < 32; kp++) {
            w0[kp] = *(const ull*)&r0[2 * kp];
            w1[kp] = *(const ull*)&r1[2 * kp];
        }
    }

    const unsigned hprt_a = cvta_smem(&hprt[0][0][0]);
    const unsigned sout_a = cvta_smem(&sout[0][0][0]);
    const unsigned bar_a  = cvta_smem(&mbarr[0]);

    // warp w sends to peer rank w: its block in peer's hprt is [.. ][jg][..]
    const unsigned peer_hprt = mapa_u32(hprt_a, w) + (unsigned)jg * 1024u;
    const unsigned peer_bar  = mapa_u32(bar_a, w);

    if (tid < 2) MBAR_INIT(bar_a + tid * 8, 1);
    if (tid == 0) {
        asm volatile("fence.mbarrier_init.release.cluster;" ::: "memory");
        MBAR_EXPECT_TX(bar_a, 8192);           // arm barrier for step 0
    }

    // output/ownership mapping: thread tid <-> (b = tid>>6, j' = tid&63)
    const int ob = tid >> 6;
    const int oj = tid & 63;
    const int gb = b0 + ob;
    const int gj = 64 * jg + oj;

    // bootstrap: own h_{-1} chunk (also the k-input chunk) into hstage[0]
    hstage[0][tid] = h0l[(size_t)gb * Hh + gj];
    __syncthreads();
    asm volatile("barrier.cluster.arrive.aligned;" ::: "memory");
    asm volatile("barrier.cluster.wait.aligned;" ::: "memory");

    unsigned par0 = 0, par1 = 0;

    for (int t = 0; t < Tt; t++) {
        const int buf = t & 1, nb = buf ^ 1;
        size_t gidx = (size_t)t * Bb * Hh + (size_t)gb * Hh + gj;
        float pre = act[gidx];                         // overlaps FFMA

        // arm next step's barrier (order-free vs completes; phase consumed)
        if (tid == 0 && t < Tt - 1)
            MBAR_EXPECT_TX(bar_a + nb * 8, 8192);

        // ---- FFMA: partial for rank w's 64 outputs over our 64-k slice ----
        const float* hb = &hstage[buf][0];
        ull a00 = 0, a01 = 0, a10 = 0, a11 = 0;
        ull a20 = 0, a21 = 0, a30 = 0, a31 = 0;
#pragma unroll
        for (int kp = 0; kp < 32; kp++) {
            ull wa = w0[kp], wb = w1[kp];
            ull hb0 = *(const ull*)&hb[0 * 64 + 2 * kp];   // lane-broadcast
            ull hb1 = *(const ull*)&hb[1 * 64 + 2 * kp];
            ull hb2 = *(const ull*)&hb[2 * 64 + 2 * kp];
            ull hb3 = *(const ull*)&hb[3 * 64 + 2 * kp];
            FMA2(a00, wa, hb0); FMA2(a01, wb, hb0);
            FMA2(a10, wa, hb1); FMA2(a11, wb, hb1);
            FMA2(a20, wa, hb2); FMA2(a21, wb, hb2);
            FMA2(a30, wa, hb3); FMA2(a31, wb, hb3);
        }

        // ---- stage + send this warp's 1KB partial block to peer w ----
        {
            float lo, hi, s0, s1;
            float* sp = &sout[buf][w][2 * lane];
            UNPK(lo, hi, a00); s0 = lo + hi; UNPK(lo, hi, a01); s1 = lo + hi;
            *(float2*)&sp[0 * 64] = make_float2(s0, s1);
            UNPK(lo, hi, a10); s0 = lo + hi; UNPK(lo, hi, a11); s1 = lo + hi;
            *(float2*)&sp[1 * 64] = make_float2(s0, s1);
            UNPK(lo, hi, a20); s0 = lo + hi; UNPK(lo, hi, a21); s1 = lo + hi;
            *(float2*)&sp[2 * 64] = make_float2(s0, s1);
            UNPK(lo, hi, a30); s0 = lo + hi; UNPK(lo, hi, a31); s1 = lo + hi;
            *(float2*)&sp[3 * 64] = make_float2(s0, s1);
        }
        __syncwarp();
        if (lane == 0) {
            asm volatile("fence.proxy.async.shared::cta;" ::: "memory");
            bulk_s2c(peer_hprt + (unsigned)buf * 8192u,
                     sout_a + (unsigned)(buf * 8192 + w * 1024),
                     1024u, peer_bar + (unsigned)buf * 8u);
        }

        // ---- wait all 8 partial blocks for our 256 outputs ----
        if (buf == 0) { MBAR_WAIT_CLUSTER(bar_a, par0); par0 ^= 1; }
        else          { MBAR_WAIT_CLUSTER(bar_a + 8, par1); par1 ^= 1; }

        float s = 0.f;
#pragma unroll
        for (int q = 0; q < 8; q++) s += hprt[buf][q][tid];

        float v = tanhf(s + pre);
        act[gidx] = v;                                  // ys in place

        if (t < Tt - 1) {
            hstage[nb][tid] = v;                        // next step's k-input
            __syncthreads();                            // the ONE sync per step
        } else {
            hout[(size_t)gb * Hh + gj] = v;             // final hidden
        }
    }

    // no peer may exit while another could still address its smem
    asm volatile("barrier.cluster.arrive.aligned;" ::: "memory");
    asm volatile("barrier.cluster.wait.aligned;" ::: "memory");
}

// ---------------- launch ----------------------------------------------------
extern "C" void kernel_launch(void* const* d_in, const int* in_sizes, int n_in,
                              void* d_out, int out_size)
{
    (void)in_sizes; (void)n_in; (void)out_size;
    const float* x     = (const float*)d_in[0];   // [T,B,IN]
    const float* h0    = (const float*)d_in[1];   // [L,B,H]
    const float* W_ih0 = (const float*)d_in[2];   // [H,IN]
    const float* W_ihr = (const float*)d_in[3];   // [L-1,H,H]
    const float* W_hh  = (const float*)d_in[4];   // [L,H,H]
    const float* b_ih  = (const float*)d_in[5];   // [L,H]
    const float* b_hh  = (const float*)d_in[6];   // [L,H]
    const float* lin_W = (const float*)d_in[7];   // [OUT,H]
    const float* lin_b = (const float*)d_in[8];   // [OUT]

    float* out   = (float*)d_out;                       // [T,B,OUT]
    float* h_out = out + (size_t)Tt * Bb * OUTN;        // [L,B,H]

    float *bufA, *bufB;
    cudaGetSymbolAddress((void**)&bufA, g_bufA);
    cudaGetSymbolAddress((void**)&bufB, g_bufB);

    dim3 blk(256);
    const int MB = (Tt * Bb) / 128;     // 256 M-blocks

    // layer 0
    sgemm_bias<INN><<<dim3(Hh / 64, MB), blk>>>(x, W_ih0, b_ih, b_hh, bufA, Hh);
    rnn_scan<<<128, blk>>>(bufA, W_hh, h0, h_out);

    // layer 1
    sgemm_bias<Hh><<<dim3(Hh / 64, MB), blk>>>(bufA, W_ihr, b_ih + Hh, b_hh + Hh,
                                               bufB, Hh);
    rnn_scan<<<128, blk>>>(bufB, W_hh + Hh * Hh, h0 + Bb * Hh, h_out + Bb * Hh);

    // layer 2
    sgemm_bias<Hh><<<dim3(Hh / 64, MB), blk>>>(bufB, W_ihr + Hh * Hh,
                                               b_ih + 2 * Hh, b_hh + 2 * Hh,
                                               bufA, Hh);
    rnn_scan<<<128, blk>>>(bufA, W_hh + 2 * Hh * Hh, h0 + 2 * Bb * Hh,
                           h_out + 2 * Bb * Hh);

    // final linear: [32768,512] @ [128,512]^T + lin_b -> d_out
    sgemm_bias<Hh><<<dim3(OUTN / 64, MB), blk>>>(bufA, lin_W, lin_b, nullptr,
                                                 out, OUTN);
}